// round 1
// baseline (speedup 1.0000x reference)
#include <cuda_runtime.h>
#include <cuda_bf16.h>

// ---------------------------------------------------------------------------
// G2EquivariantFeedForward, GB300 sm_103a
//
// Key simplification: for octonion x = r + v (v pure imaginary 7-vector),
//   x^2 = (r^2 - n^2,  2r * v)
//   x^3 = (r(r^2 - 3n^2), (3r^2 - n^2) * v),   n^2 = |v|^2
// so  upd = a*x + b*x^2 + c*x^3 = (P, Q*v) with
//   P = a*r + b*(r^2-n^2) + c*r*(r^2-3n^2)
//   Q = a + 2*b*r + c*(3r^2-n^2)
//   |upd|^2 = P^2 + Q^2*n^2
//
// Two octonions per thread, packed into f32x2 lanes; all heavy math uses
// fma.rn.f32x2 / mul.rn.f32x2 (FFMA2 — ptxas will not auto-fuse).
// GELU(exact-erf) approximated by tanh form with MUFU.TANH.
// ---------------------------------------------------------------------------

typedef unsigned long long U64;

__device__ __forceinline__ U64 pk2(float lo, float hi) {
    U64 r; asm("mov.b64 %0, {%1, %2};" : "=l"(r) : "f"(lo), "f"(hi)); return r;
}
__device__ __forceinline__ void upk2(U64 v, float& lo, float& hi) {
    asm("mov.b64 {%0, %1}, %2;" : "=f"(lo), "=f"(hi) : "l"(v));
}
__device__ __forceinline__ U64 fma2(U64 a, U64 b, U64 c) {
    U64 d; asm("fma.rn.f32x2 %0, %1, %2, %3;" : "=l"(d) : "l"(a), "l"(b), "l"(c)); return d;
}
__device__ __forceinline__ U64 mul2(U64 a, U64 b) {
    U64 d; asm("mul.rn.f32x2 %0, %1, %2;" : "=l"(d) : "l"(a), "l"(b)); return d;
}
__device__ __forceinline__ U64 add2(U64 a, U64 b) {
    U64 d; asm("add.rn.f32x2 %0, %1, %2;" : "=l"(d) : "l"(a), "l"(b)); return d;
}
__device__ __forceinline__ float tanh_ap(float x) {
    float t; asm("tanh.approx.f32 %0, %1;" : "=f"(t) : "f"(x)); return t;
}
__device__ __forceinline__ float sqrt_ap(float x) {
    float t; asm("sqrt.approx.f32 %0, %1;" : "=f"(t) : "f"(x)); return t;
}
__device__ __forceinline__ float rsqrt_ap(float x) {
    float t; asm("rsqrt.approx.f32 %0, %1;" : "=f"(t) : "f"(x)); return t;
}

__global__ __launch_bounds__(256)
void g2ff_kernel(const float4* __restrict__ in4,
                 const float*  __restrict__ W1,   // (32,2) row-major
                 const float*  __restrict__ b1,   // (32)
                 const float*  __restrict__ W2,   // (3,32) row-major
                 const float*  __restrict__ b2,   // (3)
                 const float*  __restrict__ alpha,
                 float4*       __restrict__ out4)
{
    // Shared splat-pair weight tables (each weight duplicated in both halves)
    __shared__ ulonglong2 sW1[32];    // (w0,w0 | w1,w1)
    __shared__ U64        sB1[32];    // (b1,b1)
    __shared__ ulonglong2 sW2ab[32];  // (w2a,w2a | w2b,w2b)
    __shared__ U64        sW2c[32];   // (w2c,w2c)
    __shared__ U64        sB2[3];
    __shared__ float      sScal[2];   // lam, 1-lam

    const int t = threadIdx.x;
    if (t < 32) {
        float w0 = W1[2 * t], w1 = W1[2 * t + 1];
        ulonglong2 q; q.x = pk2(w0, w0); q.y = pk2(w1, w1);
        sW1[t] = q;
        float bb = b1[t];
        sB1[t] = pk2(bb, bb);
        float wa = W2[t], wb = W2[32 + t], wc = W2[64 + t];
        ulonglong2 q2; q2.x = pk2(wa, wa); q2.y = pk2(wb, wb);
        sW2ab[t] = q2;
        sW2c[t] = pk2(wc, wc);
    } else if (t == 32) {
        float al  = alpha[0];
        float lam = 1.0f / (1.0f + __expf(-al));
        sScal[0] = lam;
        sScal[1] = 1.0f - lam;
        sB2[0] = pk2(b2[0], b2[0]);
        sB2[1] = pk2(b2[1], b2[1]);
        sB2[2] = pk2(b2[2], b2[2]);
    }
    __syncthreads();

    const int gi = blockIdx.x * 256 + t;   // thread handles octonions 2*gi, 2*gi+1

    // Load 2 octonions = 4 float4 (fully coalesced, stride 64B per thread)
    float4 A0 = in4[4 * gi + 0];
    float4 A1 = in4[4 * gi + 1];
    float4 B0 = in4[4 * gi + 2];
    float4 B1 = in4[4 * gi + 3];

    // Pack component-wise pairs (octA, octB)
    U64 p0 = pk2(A0.x, B0.x);
    U64 p1 = pk2(A0.y, B0.y);
    U64 p2 = pk2(A0.z, B0.z);
    U64 p3 = pk2(A0.w, B0.w);
    U64 p4 = pk2(A1.x, B1.x);
    U64 p5 = pk2(A1.y, B1.y);
    U64 p6 = pk2(A1.z, B1.z);
    U64 p7 = pk2(A1.w, B1.w);

    // n^2 = sum of squares of imaginary components
    U64 n2 = mul2(p1, p1);
    n2 = fma2(p2, p2, n2);
    n2 = fma2(p3, p3, n2);
    n2 = fma2(p4, p4, n2);
    n2 = fma2(p5, p5, n2);
    n2 = fma2(p6, p6, n2);
    n2 = fma2(p7, p7, n2);

    float n2l, n2h;
    upk2(n2, n2l, n2h);
    U64 np = pk2(sqrt_ap(n2l), sqrt_ap(n2h));

    // GELU-tanh constants
    const U64 C1 = pk2(0.7978845608028654f, 0.7978845608028654f);
    const U64 C2 = pk2(0.035677408136300125f, 0.035677408136300125f);
    const U64 CH = pk2(0.5f, 0.5f);

    // MLP: z = [r,n] @ W1^T + b1; h = gelu(z); scalars = h @ W2^T + b2
    U64 accA = sB2[0];
    U64 accB = sB2[1];
    U64 accC = sB2[2];

#pragma unroll
    for (int j = 0; j < 32; j++) {
        ulonglong2 w1j = sW1[j];                       // LDS.128 broadcast
        U64 z  = fma2(np, w1j.y, fma2(p0, w1j.x, sB1[j]));
        U64 z2 = mul2(z, z);
        U64 q  = fma2(z2, C2, C1);
        U64 u  = mul2(z, q);
        float ul, uh;
        upk2(u, ul, uh);
        U64 tt = pk2(tanh_ap(ul), tanh_ap(uh));        // 2x MUFU.TANH
        U64 g  = fma2(tt, CH, CH);                     // 0.5*(1+t)
        U64 h  = mul2(z, g);
        ulonglong2 w2j = sW2ab[j];                     // LDS.128 broadcast
        accA = fma2(h, w2j.x, accA);
        accB = fma2(h, w2j.y, accB);
        accC = fma2(h, sW2c[j], accC);
    }

    // Closed-form update: upd = (P, Q*v)
    const U64 N1  = pk2(-1.0f, -1.0f);
    const U64 N3  = pk2(-3.0f, -3.0f);
    const U64 TWO = pk2(2.0f, 2.0f);

    U64 r2 = mul2(p0, p0);
    U64 s2 = fma2(n2, N1, r2);            // r^2 - n^2
    U64 u3 = fma2(n2, N3, r2);            // r^2 - 3n^2
    U64 s3 = mul2(p0, u3);                // r(r^2 - 3n^2)
    U64 t3 = fma2(r2, TWO, s2);           // 3r^2 - n^2

    U64 P = fma2(accA, p0, fma2(accB, s2, mul2(accC, s3)));
    U64 tr = add2(p0, p0);
    U64 Q = fma2(accC, t3, fma2(accB, tr, accA));

    // |upd|^2 = P^2 + Q^2 * n^2 ;  inv = 1/max(|upd|, 1e-8)
    U64 ss = fma2(mul2(Q, Q), n2, mul2(P, P));
    float sl, sh;
    upk2(ss, sl, sh);
    sl = fmaxf(sl, 1e-16f);
    sh = fmaxf(sh, 1e-16f);
    U64 inv = pk2(rsqrt_ap(sl), rsqrt_ap(sh));

    float lam = sScal[0], oml = sScal[1];
    U64 LAM = pk2(lam, lam);
    U64 OML = pk2(oml, oml);

    U64 li = mul2(LAM, inv);
    U64 K  = fma2(li, Q, OML);            // coefficient for imaginary comps
    U64 o0 = fma2(li, P, mul2(p0, OML));  // scalar comp

    U64 o1 = mul2(p1, K);
    U64 o2 = mul2(p2, K);
    U64 o3 = mul2(p3, K);
    U64 o4 = mul2(p4, K);
    U64 o5 = mul2(p5, K);
    U64 o6 = mul2(p6, K);
    U64 o7 = mul2(p7, K);

    float4 OA0, OA1, OB0, OB1;
    upk2(o0, OA0.x, OB0.x);
    upk2(o1, OA0.y, OB0.y);
    upk2(o2, OA0.z, OB0.z);
    upk2(o3, OA0.w, OB0.w);
    upk2(o4, OA1.x, OB1.x);
    upk2(o5, OA1.y, OB1.y);
    upk2(o6, OA1.z, OB1.z);
    upk2(o7, OA1.w, OB1.w);

    out4[4 * gi + 0] = OA0;
    out4[4 * gi + 1] = OA1;
    out4[4 * gi + 2] = OB0;
    out4[4 * gi + 3] = OB1;
}

extern "C" void kernel_launch(void* const* d_in, const int* in_sizes, int n_in,
                              void* d_out, int out_size)
{
    const float* o     = (const float*)d_in[0];
    const float* W1    = (const float*)d_in[1];
    const float* b1    = (const float*)d_in[2];
    const float* W2    = (const float*)d_in[3];
    const float* b2    = (const float*)d_in[4];
    const float* alpha = (const float*)d_in[5];

    const int total   = in_sizes[0];        // 16*4096*512 = 33,554,432 floats
    const int threads = total / 16;         // 2 octonions (16 floats) per thread
    const int blocks  = threads / 256;      // exact: 8192

    g2ff_kernel<<<blocks, 256>>>((const float4*)o, W1, b1, W2, b2, alpha,
                                 (float4*)d_out);
}

// round 2
// speedup vs baseline: 1.2281x; 1.2281x over previous
#include <cuda_runtime.h>
#include <cuda_bf16.h>

// ---------------------------------------------------------------------------
// G2EquivariantFeedForward, GB300 sm_103a — round 2
//
// Closed form: for octonion x = r + v (v pure imaginary),
//   upd = a*x + b*x^2 + c*x^3 = (P, Q*v),
//   P = a*r + b*(r^2-n^2) + c*r*(r^2-3n^2)
//   Q = a + 2*b*r + c*(3r^2-n^2),   n^2 = |v|^2,  |upd|^2 = P^2 + Q^2 n^2
//
// This round: 4 octonions/thread as two f32x2 streams sharing each weight
// fetch (3x LDS.128 per MLP iteration instead of 4 loads per 2 octonions),
// imaginary components staged in conflict-free shared (stride 15 U64) to
// keep register pressure down.
// ---------------------------------------------------------------------------

typedef unsigned long long U64;

__device__ __forceinline__ U64 pk2(float lo, float hi) {
    U64 r; asm("mov.b64 %0, {%1, %2};" : "=l"(r) : "f"(lo), "f"(hi)); return r;
}
__device__ __forceinline__ void upk2(U64 v, float& lo, float& hi) {
    asm("mov.b64 {%0, %1}, %2;" : "=f"(lo), "=f"(hi) : "l"(v));
}
__device__ __forceinline__ U64 fma2(U64 a, U64 b, U64 c) {
    U64 d; asm("fma.rn.f32x2 %0, %1, %2, %3;" : "=l"(d) : "l"(a), "l"(b), "l"(c)); return d;
}
__device__ __forceinline__ U64 mul2(U64 a, U64 b) {
    U64 d; asm("mul.rn.f32x2 %0, %1, %2;" : "=l"(d) : "l"(a), "l"(b)); return d;
}
__device__ __forceinline__ U64 add2(U64 a, U64 b) {
    U64 d; asm("add.rn.f32x2 %0, %1, %2;" : "=l"(d) : "l"(a), "l"(b)); return d;
}
__device__ __forceinline__ float tanh_ap(float x) {
    float t; asm("tanh.approx.f32 %0, %1;" : "=f"(t) : "f"(x)); return t;
}
__device__ __forceinline__ float sqrt_ap(float x) {
    float t; asm("sqrt.approx.f32 %0, %1;" : "=f"(t) : "f"(x)); return t;
}
__device__ __forceinline__ float rsqrt_ap(float x) {
    float t; asm("rsqrt.approx.f32 %0, %1;" : "=f"(t) : "f"(x)); return t;
}

#define TPB 128          // threads per block
#define OPB 512          // octonions per block (4 per thread)
#define SLOT 15          // U64 stride per thread in staging buffer (odd*? -> conflict-free 64b)

struct Oct2 {            // one f32x2 stream = 2 octonions packed lane-wise
    U64 p0, n2, np;      // live through the MLP loop
};

__global__ __launch_bounds__(TPB)
void g2ff_kernel(const float4* __restrict__ in4,
                 const float*  __restrict__ W1,   // (32,2) row-major
                 const float*  __restrict__ b1,   // (32)
                 const float*  __restrict__ W2,   // (3,32) row-major
                 const float*  __restrict__ b2,   // (3)
                 const float*  __restrict__ alpha,
                 float4*       __restrict__ out4)
{
    __shared__ ulonglong2 sW1[32];   // (w0,w0 | w1,w1)
    __shared__ ulonglong2 sBW[32];   // (b1,b1 | w2c,w2c)
    __shared__ ulonglong2 sW2[32];   // (w2a,w2a | w2b,w2b)
    __shared__ U64        sB2[3];
    __shared__ float      sScal[2];
    __shared__ U64        sImag[TPB * SLOT];   // 14 U64 used per thread

    const int t = threadIdx.x;
    if (t < 32) {
        float w0 = W1[2 * t], w1 = W1[2 * t + 1];
        ulonglong2 q; q.x = pk2(w0, w0); q.y = pk2(w1, w1);
        sW1[t] = q;
        float bb = b1[t], wc = W2[64 + t];
        ulonglong2 qb; qb.x = pk2(bb, bb); qb.y = pk2(wc, wc);
        sBW[t] = qb;
        float wa = W2[t], wb = W2[32 + t];
        ulonglong2 q2; q2.x = pk2(wa, wa); q2.y = pk2(wb, wb);
        sW2[t] = q2;
    } else if (t == 32) {
        float al  = alpha[0];
        float lam = 1.0f / (1.0f + __expf(-al));
        sScal[0] = lam;
        sScal[1] = 1.0f - lam;
        sB2[0] = pk2(b2[0], b2[0]);
        sB2[1] = pk2(b2[1], b2[1]);
        sB2[2] = pk2(b2[2], b2[2]);
    }
    __syncthreads();

    const int base = blockIdx.x * OPB;
    // Stream X: octonions (base+t, base+128+t); stream Y: (base+256+t, base+384+t)
    const int mA = base + t;
    const int mB = base + TPB + t;
    const int mC = base + 2 * TPB + t;
    const int mD = base + 3 * TPB + t;

    U64* myImag = &sImag[t * SLOT];

    Oct2 X, Y;

    // ---- load + pack + n^2 + stage imaginaries, stream X ----
    {
        float4 A0 = in4[2 * mA + 0];
        float4 A1 = in4[2 * mA + 1];
        float4 B0 = in4[2 * mB + 0];
        float4 B1 = in4[2 * mB + 1];
        X.p0 = pk2(A0.x, B0.x);
        U64 p1 = pk2(A0.y, B0.y);
        U64 p2 = pk2(A0.z, B0.z);
        U64 p3 = pk2(A0.w, B0.w);
        U64 p4 = pk2(A1.x, B1.x);
        U64 p5 = pk2(A1.y, B1.y);
        U64 p6 = pk2(A1.z, B1.z);
        U64 p7 = pk2(A1.w, B1.w);
        U64 n2 = mul2(p1, p1);
        n2 = fma2(p2, p2, n2);
        n2 = fma2(p3, p3, n2);
        n2 = fma2(p4, p4, n2);
        n2 = fma2(p5, p5, n2);
        n2 = fma2(p6, p6, n2);
        n2 = fma2(p7, p7, n2);
        X.n2 = n2;
        float nl, nh; upk2(n2, nl, nh);
        X.np = pk2(sqrt_ap(nl), sqrt_ap(nh));
        myImag[0] = p1; myImag[1] = p2; myImag[2] = p3; myImag[3] = p4;
        myImag[4] = p5; myImag[5] = p6; myImag[6] = p7;
    }
    // ---- stream Y ----
    {
        float4 A0 = in4[2 * mC + 0];
        float4 A1 = in4[2 * mC + 1];
        float4 B0 = in4[2 * mD + 0];
        float4 B1 = in4[2 * mD + 1];
        Y.p0 = pk2(A0.x, B0.x);
        U64 p1 = pk2(A0.y, B0.y);
        U64 p2 = pk2(A0.z, B0.z);
        U64 p3 = pk2(A0.w, B0.w);
        U64 p4 = pk2(A1.x, B1.x);
        U64 p5 = pk2(A1.y, B1.y);
        U64 p6 = pk2(A1.z, B1.z);
        U64 p7 = pk2(A1.w, B1.w);
        U64 n2 = mul2(p1, p1);
        n2 = fma2(p2, p2, n2);
        n2 = fma2(p3, p3, n2);
        n2 = fma2(p4, p4, n2);
        n2 = fma2(p5, p5, n2);
        n2 = fma2(p6, p6, n2);
        n2 = fma2(p7, p7, n2);
        Y.n2 = n2;
        float nl, nh; upk2(n2, nl, nh);
        Y.np = pk2(sqrt_ap(nl), sqrt_ap(nh));
        myImag[7]  = p1; myImag[8]  = p2; myImag[9]  = p3; myImag[10] = p4;
        myImag[11] = p5; myImag[12] = p6; myImag[13] = p7;
    }

    // GELU-tanh constants
    const U64 C1 = pk2(0.7978845608028654f, 0.7978845608028654f);
    const U64 C2 = pk2(0.035677408136300125f, 0.035677408136300125f);
    const U64 CH = pk2(0.5f, 0.5f);

    U64 aAX = sB2[0], aBX = sB2[1], aCX = sB2[2];
    U64 aAY = sB2[0], aBY = sB2[1], aCY = sB2[2];

#pragma unroll
    for (int j = 0; j < 32; j++) {
        ulonglong2 w1j = sW1[j];     // LDS.128 broadcast
        ulonglong2 bwj = sBW[j];     // LDS.128 broadcast
        ulonglong2 w2j = sW2[j];     // LDS.128 broadcast

        // stream X
        {
            U64 z  = fma2(X.np, w1j.y, fma2(X.p0, w1j.x, bwj.x));
            U64 z2 = mul2(z, z);
            U64 q  = fma2(z2, C2, C1);
            U64 u  = mul2(z, q);
            float ul, uh; upk2(u, ul, uh);
            U64 tt = pk2(tanh_ap(ul), tanh_ap(uh));
            U64 hz = mul2(z, CH);
            U64 h  = fma2(hz, tt, hz);
            aAX = fma2(h, w2j.x, aAX);
            aBX = fma2(h, w2j.y, aBX);
            aCX = fma2(h, bwj.y, aCX);
        }
        // stream Y
        {
            U64 z  = fma2(Y.np, w1j.y, fma2(Y.p0, w1j.x, bwj.x));
            U64 z2 = mul2(z, z);
            U64 q  = fma2(z2, C2, C1);
            U64 u  = mul2(z, q);
            float ul, uh; upk2(u, ul, uh);
            U64 tt = pk2(tanh_ap(ul), tanh_ap(uh));
            U64 hz = mul2(z, CH);
            U64 h  = fma2(hz, tt, hz);
            aAY = fma2(h, w2j.x, aAY);
            aBY = fma2(h, w2j.y, aBY);
            aCY = fma2(h, bwj.y, aCY);
        }
    }

    const U64 N1  = pk2(-1.0f, -1.0f);
    const U64 N3  = pk2(-3.0f, -3.0f);
    const U64 TWO = pk2(2.0f, 2.0f);

    const float lam = sScal[0], oml = sScal[1];
    const U64 LAM = pk2(lam, lam);
    const U64 OML = pk2(oml, oml);

    // ---- epilogue stream X ----
    {
        U64 r2 = mul2(X.p0, X.p0);
        U64 s2 = fma2(X.n2, N1, r2);
        U64 u3 = fma2(X.n2, N3, r2);
        U64 s3 = mul2(X.p0, u3);
        U64 t3 = fma2(r2, TWO, s2);
        U64 P  = fma2(aAX, X.p0, fma2(aBX, s2, mul2(aCX, s3)));
        U64 tr = add2(X.p0, X.p0);
        U64 Q  = fma2(aCX, t3, fma2(aBX, tr, aAX));
        U64 ss = fma2(mul2(Q, Q), X.n2, mul2(P, P));
        float sl, sh; upk2(ss, sl, sh);
        sl = fmaxf(sl, 1e-16f);
        sh = fmaxf(sh, 1e-16f);
        U64 inv = pk2(rsqrt_ap(sl), rsqrt_ap(sh));
        U64 li = mul2(LAM, inv);
        U64 K  = fma2(li, Q, OML);
        U64 o0 = fma2(li, P, mul2(X.p0, OML));

        U64 o1 = mul2(myImag[0], K);
        U64 o2 = mul2(myImag[1], K);
        U64 o3 = mul2(myImag[2], K);
        U64 o4 = mul2(myImag[3], K);
        U64 o5 = mul2(myImag[4], K);
        U64 o6 = mul2(myImag[5], K);
        U64 o7 = mul2(myImag[6], K);

        float4 OA0, OA1, OB0, OB1;
        upk2(o0, OA0.x, OB0.x);
        upk2(o1, OA0.y, OB0.y);
        upk2(o2, OA0.z, OB0.z);
        upk2(o3, OA0.w, OB0.w);
        upk2(o4, OA1.x, OB1.x);
        upk2(o5, OA1.y, OB1.y);
        upk2(o6, OA1.z, OB1.z);
        upk2(o7, OA1.w, OB1.w);
        out4[2 * mA + 0] = OA0;
        out4[2 * mA + 1] = OA1;
        out4[2 * mB + 0] = OB0;
        out4[2 * mB + 1] = OB1;
    }
    // ---- epilogue stream Y ----
    {
        U64 r2 = mul2(Y.p0, Y.p0);
        U64 s2 = fma2(Y.n2, N1, r2);
        U64 u3 = fma2(Y.n2, N3, r2);
        U64 s3 = mul2(Y.p0, u3);
        U64 t3 = fma2(r2, TWO, s2);
        U64 P  = fma2(aAY, Y.p0, fma2(aBY, s2, mul2(aCY, s3)));
        U64 tr = add2(Y.p0, Y.p0);
        U64 Q  = fma2(aCY, t3, fma2(aBY, tr, aAY));
        U64 ss = fma2(mul2(Q, Q), Y.n2, mul2(P, P));
        float sl, sh; upk2(ss, sl, sh);
        sl = fmaxf(sl, 1e-16f);
        sh = fmaxf(sh, 1e-16f);
        U64 inv = pk2(rsqrt_ap(sl), rsqrt_ap(sh));
        U64 li = mul2(LAM, inv);
        U64 K  = fma2(li, Q, OML);
        U64 o0 = fma2(li, P, mul2(Y.p0, OML));

        U64 o1 = mul2(myImag[7],  K);
        U64 o2 = mul2(myImag[8],  K);
        U64 o3 = mul2(myImag[9],  K);
        U64 o4 = mul2(myImag[10], K);
        U64 o5 = mul2(myImag[11], K);
        U64 o6 = mul2(myImag[12], K);
        U64 o7 = mul2(myImag[13], K);

        float4 OA0, OA1, OB0, OB1;
        upk2(o0, OA0.x, OB0.x);
        upk2(o1, OA0.y, OB0.y);
        upk2(o2, OA0.z, OB0.z);
        upk2(o3, OA0.w, OB0.w);
        upk2(o4, OA1.x, OB1.x);
        upk2(o5, OA1.y, OB1.y);
        upk2(o6, OA1.z, OB1.z);
        upk2(o7, OA1.w, OB1.w);
        out4[2 * mC + 0] = OA0;
        out4[2 * mC + 1] = OA1;
        out4[2 * mD + 0] = OB0;
        out4[2 * mD + 1] = OB1;
    }
}

extern "C" void kernel_launch(void* const* d_in, const int* in_sizes, int n_in,
                              void* d_out, int out_size)
{
    const float* o     = (const float*)d_in[0];
    const float* W1    = (const float*)d_in[1];
    const float* b1    = (const float*)d_in[2];
    const float* W2    = (const float*)d_in[3];
    const float* b2    = (const float*)d_in[4];
    const float* alpha = (const float*)d_in[5];

    const int total = in_sizes[0];          // 33,554,432 floats
    const int octs  = total / 8;            // 4,194,304 octonions
    const int blocks = octs / OPB;          // 8192

    g2ff_kernel<<<blocks, TPB>>>((const float4*)o, W1, b1, W2, b2, alpha,
                                 (float4*)d_out);
}